// round 17
// baseline (speedup 1.0000x reference)
#include <cuda_runtime.h>
#include <cuda_bf16.h>
#include <cstdint>

#define L2E 1.4426950408889634f
#define BATCH 64
#define SEQ 512
#define HID 768
#define NC 21
#define EM_STRIDE (SEQ * NC)

#define BM 64
#define TSTRIDE 144           // bf16 tile row stride: 4 slots x 16 cols + pad
#define NFRAG (48 * 3)        // 48 k16 tiles x 3 n8 tiles

__device__ __align__(16) float g_emx[BATCH * SEQ * NC];   // linear emissions 2^em2
__device__ __align__(16) uint32_t g_wfrag[NFRAG * 64];    // W bf16, mma-frag order
__device__ __align__(16) float g_half[BATCH][2][24];      // fwd/bwd half vectors
__device__ float g_hoffe[BATCH][2];
__device__ float g_num[BATCH];
__device__ float g_res[BATCH];
__device__ int g_bcnt[BATCH];   // gemm arrivals (roles); reset by role 7
__device__ int g_scnt[BATCH];   // publishes; reset by combiner
__device__ int g_done;          // combines; reset by final reducer

__device__ __forceinline__ float fast_ex2(float x) {
    float y; asm("ex2.approx.ftz.f32 %0, %1;" : "=f"(y) : "f"(x)); return y;
}
__device__ __forceinline__ float fast_lg2(float x) {
    float y; asm("lg2.approx.ftz.f32 %0, %1;" : "=f"(y) : "f"(x)); return y;
}
__device__ __forceinline__ uint32_t smem_u32(const void* p) {
    uint32_t a;
    asm("{ .reg .u64 t; cvta.to.shared.u64 t, %1; cvt.u32.u64 %0, t; }" : "=r"(a) : "l"(p));
    return a;
}
__device__ __forceinline__ void cp_async16(void* dst, const void* src) {
    unsigned d = (unsigned)__cvta_generic_to_shared(dst);
    asm volatile("cp.async.cg.shared.global [%0], [%1], 16;" :: "r"(d), "l"(src));
}
#define PACK2(d, lo, hi) asm("mov.b64 %0, {%1, %2};" : "=l"(d) : "f"(lo), "f"(hi))
#define MUL2(d, a, b)    asm("mul.rn.f32x2 %0, %1, %2;" : "=l"(d) : "l"(a), "l"(b))
#define FMA2(d, a, b)    asm("fma.rn.f32x2 %0, %1, %2, %3;" : "=l"(d) : "l"(a), "l"(b), "l"(d))
#define ADD2(d, a, b)    asm("add.rn.f32x2 %0, %1, %2;" : "=l"(d) : "l"(a), "l"(b))
#define UNPACK2(lo, hi, s) asm("mov.b64 {%0, %1}, %2;" : "=f"(lo), "=f"(hi) : "l"(s))

// ---------------------------------------------------------------------------
// Kernel 0: pack W into mma B-fragment order (proven).
// ---------------------------------------------------------------------------
__global__ void pack_w_kernel(const float* __restrict__ W) {
    int o = blockIdx.x * blockDim.x + threadIdx.x;
    if (o >= NFRAG * 64) return;
    int h    = o & 1;
    int lane = (o >> 1) & 31;
    int f    = o >> 6;
    int nt   = f % 3;
    int kc   = f / 3;                 // k16 tile 0..47
    int k    = kc * 16 + (lane & 3) * 2 + h * 8;
    int n    = nt * 8 + (lane >> 2);
    float w0 = (n < NC) ? W[k * NC + n]       : 0.f;
    float w1 = (n < NC) ? W[(k + 1) * NC + n] : 0.f;
    uint32_t pk;
    asm("cvt.rn.satfinite.bf16x2.f32 %0, %1, %2;" : "=r"(pk) : "f"(w1), "f"(w0));
    g_wfrag[o] = pk;
}

#define MATVEC2(RES, u0, u1, u2, m2) do {                                   \
    uint64_t _a0, _a1;                                                       \
    MUL2(_a0, u0.x, m2[0]);  MUL2(_a1, u0.y, m2[1]);                         \
    FMA2(_a0, u1.x, m2[2]);  FMA2(_a1, u1.y, m2[3]);                         \
    FMA2(_a0, u2.x, m2[4]);  FMA2(_a1, u2.y, m2[5]);                         \
    FMA2(_a0, u3.x, m2[6]);  FMA2(_a1, u3.y, m2[7]);                         \
    FMA2(_a0, u4.x, m2[8]);  FMA2(_a1, u4.y, m2[9]);                         \
    FMA2(_a0, u5.x, m2[10]); FMA2(_a1, u5.y, m2[11]);                        \
    ADD2(_a0, _a0, _a1);                                                     \
    float _lo, _hi; UNPACK2(_lo, _hi, _a0);                                  \
    RES = _lo + _hi;                                                         \
} while (0)

// ---------------------------------------------------------------------------
// Fused kernel, 512 CTAs x 256 thr. Gemm: warp (band = wid&3 -> 16 rows,
// ks = wid>>2 -> K half). Per-warp cp.async ring (depth 3, 16-col chunks),
// barrier-free mainloop; K-split partials merged via smem. Scan roles by
// gemm arrival: 5=numerator, 6=backward half, 7=forward half; last publisher
// combines, 64th combiner reduces.
// ---------------------------------------------------------------------------
#define RING_F 6144            // 3 stages x 8 warps x 256 floats
#define USM_BYTES 33792        // 24576 ring + 9216 tile
__global__ __launch_bounds__(256) void fused_kernel(
    const float* __restrict__ hidden,
    const float* __restrict__ bias,
    const float* __restrict__ start_t,
    const float* __restrict__ end_t,
    const float* __restrict__ trans,
    const int*   __restrict__ labr,
    float* __restrict__ out)
{
    __shared__ __align__(1024) uint8_t usm[USM_BYTES];
    __shared__ int s_role, s_len, s_pub, s_last;

    const int tid   = threadIdx.x;
    const int wid   = tid >> 5;
    const int lane  = tid & 31;
    const int band  = wid & 3;
    const int ks    = wid >> 2;
    const int row0  = blockIdx.x * BM;
    const int batch = blockIdx.x >> 3;

    // ================= GEMM phase =================
    float*   f32s = reinterpret_cast<float*>(usm);   // ring: [st][wid][256]
    uint8_t* tile = usm + 24576;                     // 64 rows x 144B

    float acc[3][4];
#pragma unroll
    for (int i = 0; i < 3; i++)
#pragma unroll
        for (int j = 0; j < 4; j++) acc[i][j] = 0.f;

    // chunk = 16 cols of this warp's K half; 24 chunks total
    auto issue = [&](int ch, int st) {
        const float* src0 = hidden +
            (uint64_t)(row0 + band * 16) * HID + ks * 384 + ch * 16;
        float* dst = &f32s[(st * 8 + wid) * 256];
#pragma unroll
        for (int u = 0; u < 2; u++) {
            int q = lane + u * 32;            // 0..63 (16B segs)
            int r = q >> 2, seg = q & 3;
            cp_async16(dst + q * 4, src0 + r * HID + seg * 4);
        }
        asm volatile("cp.async.commit_group;");
    };
    auto convert = [&](int ch, int st) {
        const float* src = &f32s[(st * 8 + wid) * 256];
        const int slot = (ks * 2 + (ch & 1)) * 32;   // byte offset of 16-col slot
#pragma unroll
        for (int u = 0; u < 2; u++) {
            int q = lane + u * 32;
            int r = q >> 2, seg = q & 3;
            int rr = band * 16 + r;
            float4 v = *reinterpret_cast<const float4*>(src + q * 4);
            uint32_t b0, b1;
            asm("cvt.rn.satfinite.bf16x2.f32 %0, %1, %2;" : "=r"(b0) : "f"(v.y), "f"(v.x));
            asm("cvt.rn.satfinite.bf16x2.f32 %0, %1, %2;" : "=r"(b1) : "f"(v.w), "f"(v.z));
            uint2 pk = {b0, b1};
            *reinterpret_cast<uint2*>(tile + rr * TSTRIDE + slot + seg * 8) = pk;
        }
    };

    issue(0, 0); issue(1, 1); issue(2, 2);

    const int rowA = band * 16 + (lane & 7) + ((lane >> 3) & 1) * 8;
    const int aoff = rowA * TSTRIDE + ((lane >> 4) * 16);

    for (int ch = 0; ch < 24; ch++) {
        if (ch < 22)       asm volatile("cp.async.wait_group 2;");
        else if (ch == 22) asm volatile("cp.async.wait_group 1;");
        else               asm volatile("cp.async.wait_group 0;");
        convert(ch, ch % 3);                   // warp-private rows/slots
        if (ch + 3 < 24) issue(ch + 3, ch % 3);

        const int slot = (ks * 2 + (ch & 1)) * 32;
        const uint32_t abase = smem_u32(tile) + aoff + slot;
        uint32_t a0, a1, a2, a3;
        asm volatile("ldmatrix.sync.aligned.m8n8.x4.shared.b16 {%0,%1,%2,%3}, [%4];"
            : "=r"(a0), "=r"(a1), "=r"(a2), "=r"(a3) : "r"(abase));
        const int kc = ks * 24 + ch;
        const int fbase = kc * 3 * 64 + lane * 2;
#pragma unroll
        for (int nt = 0; nt < 3; nt++) {
            uint2 b = *reinterpret_cast<const uint2*>(&g_wfrag[fbase + nt * 64]);
            asm volatile("mma.sync.aligned.m16n8k16.row.col.f32.bf16.bf16.f32 "
                "{%0,%1,%2,%3}, {%4,%5,%6,%7}, {%8,%9}, {%0,%1,%2,%3};"
                : "+f"(acc[nt][0]), "+f"(acc[nt][1]), "+f"(acc[nt][2]), "+f"(acc[nt][3])
                : "r"(a0), "r"(a1), "r"(a2), "r"(a3), "r"(b.x), "r"(b.y));
        }
    }
    __syncthreads();   // all warps done with usm before merge aliases it

    // merge K-split partials: ks=1 stores, ks=0 adds; then emx epilogue
    {
        float (*mrg)[32][12] = reinterpret_cast<float(*)[32][12]>(usm);  // 6144B
        float* smf = reinterpret_cast<float*>(usm + 8192);               // 64x21
        if (ks == 1) {
#pragma unroll
            for (int nt = 0; nt < 3; nt++)
#pragma unroll
                for (int q = 0; q < 4; q++)
                    mrg[band][lane][nt * 4 + q] = acc[nt][q];
        }
        __syncthreads();
        if (ks == 0) {
            const int r0 = band * 16 + (lane >> 2);
#pragma unroll
            for (int nt = 0; nt < 3; nt++) {
                float m0 = mrg[band][lane][nt * 4 + 0];
                float m1 = mrg[band][lane][nt * 4 + 1];
                float m2 = mrg[band][lane][nt * 4 + 2];
                float m3 = mrg[band][lane][nt * 4 + 3];
                int c = nt * 8 + (lane & 3) * 2;
                if (c < NC) {
                    float bc = bias[c];
                    smf[r0 * NC + c]       = fast_ex2((acc[nt][0] + m0 + bc) * L2E);
                    smf[(r0 + 8) * NC + c] = fast_ex2((acc[nt][2] + m2 + bc) * L2E);
                }
                if (c + 1 < NC) {
                    float bc = bias[c + 1];
                    smf[r0 * NC + c + 1]       = fast_ex2((acc[nt][1] + m1 + bc) * L2E);
                    smf[(r0 + 8) * NC + c + 1] = fast_ex2((acc[nt][3] + m3 + bc) * L2E);
                }
            }
        }
        __syncthreads();
        float4* dst = reinterpret_cast<float4*>(g_emx + (uint64_t)row0 * NC);
        const float4* src = reinterpret_cast<const float4*>(smf);
        for (int i = tid; i < (BM * NC) / 4; i += 256) dst[i] = src[i];
    }

    // ================= role assignment =================
    __threadfence();
    if (tid == 0) s_role = atomicAdd(&g_bcnt[batch], 1);
    __syncthreads();
    const int role = s_role;
    if (role == 7 && tid == 0) g_bcnt[batch] = 0;   // all 8 arrived; replay-safe
    if (role < 5) return;

    // ================= labels: dtype + len =================
    float* red_f = reinterpret_cast<float*>(usm + 21760);   // 256 floats
    int*   red_i = reinterpret_cast<int*>(usm + 22784);     // 256 ints

    int okd = 1;
    for (int t = tid; t < SEQ; t += 256) {
        int v = labr[2 * t + 1];
        if (v != 0 && v != -1) okd = 0;
    }
    __syncthreads();
    int is64 = __syncthreads_and(okd);
    const int lbase = is64 ? batch * SEQ * 2 : batch * SEQ;
    const int lstep = is64 ? 2 : 1;
#define LAB(t) labr[lbase + (t) * lstep]
    {
        int cnt = 0;
        for (int t = tid; t < SEQ; t += 256)
            if (LAB(t) != -100) cnt++;
        red_i[tid] = cnt;
        __syncthreads();
        for (int s = 128; s > 0; s >>= 1) {
            if (tid < s) red_i[tid] += red_i[tid + s];
            __syncthreads();
        }
        if (tid == 0) s_len = red_i[0];
        __syncthreads();
    }
    const int len = s_len;
    const int mid = (len + 1) >> 1;
    const float* emx_g = g_emx + batch * EM_STRIDE;

    float* emx_s    = reinterpret_cast<float*>(usm);              // <=21504 B
    float (*av)[24] = reinterpret_cast<float(*)[24]>(usm + 21504);

    if (role == 5) {
        // ---------- numerator (log2 domain) ----------
        float pa = 0.f;
        for (int t = tid; t < SEQ; t += 256) {
            int l = LAB(t);
            if (l != -100) {
                if (t == 0) {
                    pa += start_t[l] * L2E + fast_lg2(emx_g[l]);
                } else {
                    int lp = LAB(t - 1);
                    pa += fast_lg2(emx_g[t * NC + l]) + trans[lp * NC + l] * L2E;
                }
            }
        }
        red_f[tid] = pa;
        __syncthreads();
        for (int s = 128; s > 0; s >>= 1) {
            if (tid < s) red_f[tid] += red_f[tid + s];
            __syncthreads();
        }
        if (tid == 0)
            g_num[batch] = red_f[0] + end_t[LAB(len - 1)] * L2E;
    } else if (role == 7) {
        // ---------- forward scan: alpha over [0, mid) ----------
        for (int i = tid; i < mid * NC; i += 256) emx_s[i] = emx_g[i];
        __syncthreads();
        if (tid < 32) {
            const int j = lane < NC ? lane : NC - 1;
            float tl[24];
#pragma unroll
            for (int i = 0; i < NC; i++) tl[i] = fast_ex2(trans[i * NC + j] * L2E);
            tl[21] = tl[22] = tl[23] = 0.f;
            uint64_t tl2[12];
#pragma unroll
            for (int p = 0; p < 12; p++) PACK2(tl2[p], tl[2 * p], tl[2 * p + 1]);

            float a = fast_ex2(start_t[j] * L2E) * emx_s[j];
            if (lane < NC)  av[0][lane] = a;
            if (lane >= NC && lane < 24) { av[0][lane] = 0.f; av[1][lane] = 0.f; }
            int offe = 0, buf = 0;
            for (int t = 1; t < mid; t++) {
                float emn = emx_s[t * NC + j];
                __syncwarp();
                const ulonglong2* vp = reinterpret_cast<const ulonglong2*>(av[buf]);
                ulonglong2 u0 = vp[0], u1 = vp[1], u2 = vp[2];
                ulonglong2 u3 = vp[3], u4 = vp[4], u5 = vp[5];
                uint32_t lo0 = (uint32_t)u0.x;
                int   e     = (int)((lo0 >> 23) & 255) - 127;
                float sclem = __int_as_float((127 - e) << 23) * emn;
                offe += e;
                float s;
                MATVEC2(s, u0, u1, u2, tl2);
                a = s * sclem;
                buf ^= 1;
                if (lane < NC) av[buf][lane] = a;
            }
            __syncwarp();
            if (lane < 24) g_half[batch][0][lane] = (lane < NC) ? a : 0.f;
            if (lane == 0) g_hoffe[batch][0] = (float)offe;
        }
    } else {
        // ---------- backward scan: beta over [mid, len) ----------
        const int nrows = len - mid;
        for (int i = tid; i < nrows * NC; i += 256)
            emx_s[i] = emx_g[mid * NC + i];
        __syncthreads();
        if (tid < 32) {
            const int j = lane < NC ? lane : NC - 1;
            float tb[24];
#pragma unroll
            for (int k = 0; k < NC; k++) tb[k] = fast_ex2(trans[j * NC + k] * L2E);
            tb[21] = tb[22] = tb[23] = 0.f;
            uint64_t tb2[12];
#pragma unroll
            for (int p = 0; p < 12; p++) PACK2(tb2[p], tb[2 * p], tb[2 * p + 1]);

            float b = fast_ex2(end_t[j] * L2E);
            int offe = 0, buf = 0;
            if (lane >= NC && lane < 24) { av[0][lane] = 0.f; av[1][lane] = 0.f; }
            for (int t = len - 1; t >= mid; t--) {
                float d = b * emx_s[(t - mid) * NC + j];
                if (lane < NC) av[buf][lane] = d;
                __syncwarp();
                const ulonglong2* vp = reinterpret_cast<const ulonglong2*>(av[buf]);
                ulonglong2 u0 = vp[0], u1 = vp[1], u2 = vp[2];
                ulonglong2 u3 = vp[3], u4 = vp[4], u5 = vp[5];
                uint32_t lo0 = (uint32_t)u0.x;
                int   e   = (int)((lo0 >> 23) & 255) - 127;
                float scl = __int_as_float((127 - e) << 23);
                offe += e;
                float s;
                MATVEC2(s, u0, u1, u2, tb2);
                b = s * scl;
                buf ^= 1;
            }
            __syncwarp();
            if (lane < 24) g_half[batch][1][lane] = (lane < NC) ? b : 0.f;
            if (lane == 0) g_hoffe[batch][1] = (float)offe;
        }
    }
#undef LAB

    // ================= combine: last of 3 publishers =================
    __syncthreads();
    __threadfence();
    if (tid == 0) s_pub = atomicAdd(&g_scnt[batch], 1);
    __syncthreads();
    if (s_pub != 2) return;
    __threadfence();
    if (tid == 0) g_scnt[batch] = 0;                 // replay-safe

    if (tid < 32) {
        float ex = (lane < NC) ? g_half[batch][0][lane] * g_half[batch][1][lane] : 0.f;
#pragma unroll
        for (int d = 16; d > 0; d >>= 1)
            ex += __shfl_xor_sync(0xffffffffu, ex, d);
        if (lane == 0)
            g_res[batch] = g_hoffe[batch][0] + g_hoffe[batch][1] +
                           fast_lg2(ex) - g_num[batch];
    }

    // ================= final loss: 64th combiner reduces =================
    __syncthreads();
    __threadfence();
    if (tid == 0) s_last = (atomicAdd(&g_done, 1) == BATCH - 1);
    __syncthreads();
    if (s_last && tid < 32) {
        float v = g_res[tid] + g_res[tid + 32];
#pragma unroll
        for (int d = 16; d > 0; d >>= 1)
            v += __shfl_xor_sync(0xffffffffu, v, d);
        if (tid == 0) {
            out[0] = v * (1.0f / (64.0f * L2E));
            g_done = 0;                              // replay-safe
        }
    }
}

// ---------------------------------------------------------------------------
extern "C" void kernel_launch(void* const* d_in, const int* in_sizes, int n_in,
                              void* d_out, int out_size)
{
    const float* hidden = nullptr;
    const float* W      = nullptr;
    const float* trans  = nullptr;
    const int*   labels = nullptr;
    const float* small[3] = {nullptr, nullptr, nullptr};
    int nsmall = 0;

    for (int i = 0; i < n_in; i++) {
        switch (in_sizes[i]) {
            case BATCH * SEQ * HID: hidden = (const float*)d_in[i]; break;
            case HID * NC:          W      = (const float*)d_in[i]; break;
            case NC * NC:           trans  = (const float*)d_in[i]; break;
            case BATCH * SEQ:       labels = (const int*)d_in[i];   break;
            case NC: if (nsmall < 3) small[nsmall++] = (const float*)d_in[i]; break;
            default: break;
        }
    }
    const float* bias    = small[0];
    const float* start_t = small[1];
    const float* end_t   = small[2];

    pack_w_kernel<<<(NFRAG * 64 + 255) / 256, 256>>>(W);
    fused_kernel<<<512, 256>>>(hidden, bias, start_t, end_t, trans, labels,
                               (float*)d_out);
}